// round 4
// baseline (speedup 1.0000x reference)
#include <cuda_runtime.h>
#include <math.h>
#include <stdint.h>

#define NTOK  32768
#define CH    128
#define CF    512
#define JQKV  384
#define NHEADS 8
#define HD    16

// smem tile geometry: BM=128, BN=64, BK=32, stride 36 (36 % 32 == 4 -> conflict-free)
#define AS_SZ (128 * 36)
#define BS_SZ (64 * 36)
#define SMEM_BYTES ((2 * AS_SZ + 2 * BS_SZ) * 4)

// ---------------- scratch (device globals; no runtime allocation) ----------------
__device__ float g_xT[NTOK * CH];      // x transposed to (N, C)
__device__ float g_qkv[NTOK * JQKV];   // (N, 384)
__device__ float g_attn[NTOK * CH];    // (N, 128)
__device__ float g_y[NTOK * CH];       // proj out (N, 128)
__device__ float g_h[NTOK * CF];       // ffn hidden (N, 512)
__device__ float g_z[NTOK * CH];       // ffn out + residual (N, 128)
__device__ float g_sum1[CH], g_sq1[CH], g_sum2[CH], g_sq2[CH];
__device__ float g_m1[CH], g_i1[CH], g_m2[CH], g_i2[CH];

// ---------------- zero stats ----------------
__global__ void zero_stats_kernel() {
    int t = threadIdx.x;
    if (t < CH) { g_sum1[t] = 0.f; g_sq1[t] = 0.f; g_sum2[t] = 0.f; g_sq2[t] = 0.f; }
}

// ---------------- helpers ----------------
__device__ __forceinline__ void split_tf32(float x, uint32_t& hi, uint32_t& lo) {
    uint32_t h;
    asm("cvt.rna.tf32.f32 %0, %1;" : "=r"(h) : "f"(x));
    float hf = __uint_as_float(h);
    uint32_t l;
    asm("cvt.rna.tf32.f32 %0, %1;" : "=r"(l) : "f"(x - hf));
    hi = h; lo = l;
}

__device__ __forceinline__ void mma_tf32(float c[4], const uint32_t a[4], const uint32_t b[2]) {
    asm volatile(
        "mma.sync.aligned.m16n8k8.row.col.f32.tf32.tf32.f32 "
        "{%0,%1,%2,%3}, {%4,%5,%6,%7}, {%8,%9}, {%0,%1,%2,%3};\n"
        : "+f"(c[0]), "+f"(c[1]), "+f"(c[2]), "+f"(c[3])
        : "r"(a[0]), "r"(a[1]), "r"(a[2]), "r"(a[3]), "r"(b[0]), "r"(b[1]));
}

__device__ __forceinline__ void cp_async16(float* smem_ptr, const float* gptr) {
    uint32_t s = (uint32_t)__cvta_generic_to_shared(smem_ptr);
    asm volatile("cp.async.ca.shared.global [%0], [%1], 16;" :: "r"(s), "l"(gptr));
}
__device__ __forceinline__ void cp_commit() {
    asm volatile("cp.async.commit_group;");
}
template<int N>
__device__ __forceinline__ void cp_wait() {
    asm volatile("cp.async.wait_group %0;" :: "n"(N));
}

// ---------------- transpose x (C,N) -> (N,C) ----------------
__global__ void transpose_x_kernel(const float* __restrict__ x, float* __restrict__ xT)
{
    __shared__ float tile[32][33];
    const int n0 = blockIdx.x * 32, c0 = blockIdx.y * 32;
    const int tx = threadIdx.x, ty = threadIdx.y;   // (32, 8)
    #pragma unroll
    for (int i = 0; i < 4; i++) {
        int cc = ty + i * 8;
        tile[cc][tx] = x[(size_t)(c0 + cc) * NTOK + n0 + tx];
    }
    __syncthreads();
    #pragma unroll
    for (int i = 0; i < 4; i++) {
        int nn = ty + i * 8;
        xT[(size_t)(n0 + nn) * CH + c0 + tx] = tile[tx][nn];
    }
}

// ---------------- tensor-core TF32 GEMM, cp.async double-buffered ----------------
// out[m][j] = sum_k A[m][k] * W[j][k] + bias[j]   (A row-major (M,K), W row-major (J,K))
// NORMA: normalize A on load (per-k mean/istd). EPI: 0 bias; 1 gelu; 2 +norm residual
// 128 threads (4 warps), BM=128, BN=64, BK=32, warp tile 64x32.
template<bool NORMA, int EPI>
__global__ void __launch_bounds__(128) gemm_tc(const float* __restrict__ A,
                                               const float* __restrict__ W,
                                               const float* __restrict__ bias,
                                               float* __restrict__ out,
                                               int M, int Kd, int Jd,
                                               const float* __restrict__ nmean,
                                               const float* __restrict__ nistd,
                                               const float* __restrict__ res)
{
    extern __shared__ float sm[];
    float* As = sm;                 // 2 stages of [128][36]
    float* Bs = sm + 2 * AS_SZ;     // 2 stages of [64][36]

    const int tid  = threadIdx.x;
    const int wid  = tid >> 5, lane = tid & 31;
    const int l4   = lane >> 2, q = lane & 3;
    const int wm   = wid & 1, wn = wid >> 1;
    const int m0   = blockIdx.x * 128, j0 = blockIdx.y * 64;

    float c[4][4][4];
    #pragma unroll
    for (int mi = 0; mi < 4; mi++)
        #pragma unroll
        for (int ni = 0; ni < 4; ni++)
            #pragma unroll
            for (int r = 0; r < 4; r++) c[mi][ni][r] = 0.f;

    const int nT = Kd >> 5;

    // stage(s, k0): A tile 128x32 (1024 f4), B tile 64x32 (512 f4)
    auto stage = [&](int s, int k0) {
        float* As_ = As + s * AS_SZ;
        float* Bs_ = Bs + s * BS_SZ;
        #pragma unroll
        for (int i = 0; i < 8; i++) {
            int f4 = i * 128 + tid;
            int row = f4 >> 3, kq = (f4 & 7) << 2;
            cp_async16(&As_[row * 36 + kq], &A[(size_t)(m0 + row) * Kd + k0 + kq]);
        }
        #pragma unroll
        for (int i = 0; i < 4; i++) {
            int f4 = i * 128 + tid;
            int row = f4 >> 3, kq = (f4 & 7) << 2;
            cp_async16(&Bs_[row * 36 + kq], &W[(size_t)(j0 + row) * Kd + k0 + kq]);
        }
        cp_commit();
    };

    stage(0, 0);
    int buf = 0;
    for (int t = 0; t < nT; t++) {
        if (t + 1 < nT) { stage(buf ^ 1, (t + 1) << 5); cp_wait<1>(); }
        else            { cp_wait<0>(); }
        __syncthreads();

        const float* As_ = As + buf * AS_SZ;
        const float* Bs_ = Bs + buf * BS_SZ;
        const int k0 = t << 5;

        #pragma unroll
        for (int g = 0; g < 4; g++) {
            const int kq = g * 8 + q;
            float nm0, ni0, nm1, ni1;
            if (NORMA) {
                nm0 = nmean[k0 + kq];     ni0 = nistd[k0 + kq];
                nm1 = nmean[k0 + kq + 4]; ni1 = nistd[k0 + kq + 4];
            }
            uint32_t bh[4][2], bl[4][2];
            #pragma unroll
            for (int ni = 0; ni < 4; ni++) {
                int col = wn * 32 + ni * 8 + l4;
                float f0 = Bs_[col * 36 + kq];
                float f1 = Bs_[col * 36 + kq + 4];
                split_tf32(f0, bh[ni][0], bl[ni][0]);
                split_tf32(f1, bh[ni][1], bl[ni][1]);
            }
            #pragma unroll
            for (int mi = 0; mi < 4; mi++) {
                int r0 = wm * 64 + mi * 16 + l4;
                float f0 = As_[r0 * 36 + kq];
                float f1 = As_[(r0 + 8) * 36 + kq];
                float f2 = As_[r0 * 36 + kq + 4];
                float f3 = As_[(r0 + 8) * 36 + kq + 4];
                if (NORMA) {
                    f0 = (f0 - nm0) * ni0; f1 = (f1 - nm0) * ni0;
                    f2 = (f2 - nm1) * ni1; f3 = (f3 - nm1) * ni1;
                }
                uint32_t ah[4], al[4];
                split_tf32(f0, ah[0], al[0]);
                split_tf32(f1, ah[1], al[1]);
                split_tf32(f2, ah[2], al[2]);
                split_tf32(f3, ah[3], al[3]);
                #pragma unroll
                for (int ni = 0; ni < 4; ni++) {
                    mma_tf32(c[mi][ni], ah, bh[ni]);   // hi*hi
                    mma_tf32(c[mi][ni], al, bh[ni]);   // lo*hi
                    mma_tf32(c[mi][ni], ah, bl[ni]);   // hi*lo
                }
            }
        }
        __syncthreads();
        buf ^= 1;
    }

    // ---- epilogue ----
    #pragma unroll
    for (int ni = 0; ni < 4; ni++) {
        int j = j0 + wn * 32 + ni * 8 + q * 2;
        float b0 = bias[j], b1 = bias[j + 1];
        float im0 = 0.f, ii0 = 0.f, im1 = 0.f, ii1 = 0.f;
        if (EPI == 2) { im0 = nmean[j]; ii0 = nistd[j]; im1 = nmean[j + 1]; ii1 = nistd[j + 1]; }
        #pragma unroll
        for (int mi = 0; mi < 4; mi++) {
            int r0 = m0 + wm * 64 + mi * 16 + l4;
            #pragma unroll
            for (int half = 0; half < 2; half++) {
                int m = r0 + half * 8;
                float v0 = c[mi][ni][half * 2 + 0] + b0;
                float v1 = c[mi][ni][half * 2 + 1] + b1;
                if (EPI == 1) {
                    float u = v0;
                    v0 = 0.5f * u * (1.f + tanhf(0.7978845608028654f * (u + 0.044715f * u * u * u)));
                    u = v1;
                    v1 = 0.5f * u * (1.f + tanhf(0.7978845608028654f * (u + 0.044715f * u * u * u)));
                } else if (EPI == 2) {
                    float2 r2 = *(const float2*)&res[(size_t)m * Jd + j];
                    v0 += (r2.x - im0) * ii0;
                    v1 += (r2.y - im1) * ii1;
                }
                *(float2*)&out[(size_t)m * Jd + j] = make_float2(v0, v1);
            }
        }
    }
}

// ---------------- neighborhood attention: one warp per token ----------------
__global__ void attn_kernel(const float* __restrict__ qkv, const float* __restrict__ rpb,
                            float* __restrict__ out)
{
    __shared__ float rpb_s[NHEADS * 125];
    const int tid = threadIdx.x;
    for (int i = tid; i < NHEADS * 125; i += 256) rpb_s[i] = rpb[i];
    __syncthreads();

    const int warp = tid >> 5, lane = tid & 31;
    const int n = blockIdx.x * 8 + warp;
    const int h = lane >> 2, p = lane & 3;

    const int hh = n >> 10, ww = (n >> 5) & 31, zz = n & 31;
    const int sh = min(max(hh - 1, 0), 29);
    const int sw = min(max(ww - 1, 0), 29);
    const int sz = min(max(zz - 1, 0), 29);
    const int bh = sh - hh + 2, bw = sw - ww + 2, bz = sz - zz + 2;

    float4 q4 = *(const float4*)&qkv[(size_t)n * JQKV + h * 16 + p * 4];
    const float qx = q4.x * 0.25f, qy = q4.y * 0.25f, qz = q4.z * 0.25f, qw = q4.w * 0.25f;

    const float* rb = &rpb_s[h * 125];
    float s[27];
    #pragma unroll
    for (int j = 0; j < 27; j++) {
        int kh = j / 9, kw = (j / 3) % 3, kz = j % 3;
        int nb = ((sh + kh) << 10) + ((sw + kw) << 5) + (sz + kz);
        float4 k4 = *(const float4*)&qkv[(size_t)nb * JQKV + 128 + h * 16 + p * 4];
        float d = qx * k4.x + qy * k4.y + qz * k4.z + qw * k4.w;
        d += __shfl_xor_sync(0xffffffffu, d, 1);
        d += __shfl_xor_sync(0xffffffffu, d, 2);
        s[j] = d + rb[(bh + kh) * 25 + (bw + kw) * 5 + (bz + kz)];
    }

    float mx = -1e30f;
    #pragma unroll
    for (int j = 0; j < 27; j++) mx = fmaxf(mx, s[j]);
    float sum = 0.f;
    #pragma unroll
    for (int j = 0; j < 27; j++) { s[j] = expf(s[j] - mx); sum += s[j]; }
    const float inv = 1.f / sum;

    float ox = 0.f, oy = 0.f, oz = 0.f, ow = 0.f;
    #pragma unroll
    for (int j = 0; j < 27; j++) {
        int kh = j / 9, kw = (j / 3) % 3, kz = j % 3;
        int nb = ((sh + kh) << 10) + ((sw + kw) << 5) + (sz + kz);
        float4 v4 = *(const float4*)&qkv[(size_t)nb * JQKV + 256 + h * 16 + p * 4];
        float pj = s[j] * inv;
        ox = fmaf(pj, v4.x, ox); oy = fmaf(pj, v4.y, oy);
        oz = fmaf(pj, v4.z, oz); ow = fmaf(pj, v4.w, ow);
    }
    *(float4*)&out[(size_t)n * CH + h * 16 + p * 4] = make_float4(ox, oy, oz, ow);
}

// ---------------- per-channel sum/sumsq over tokens ----------------
__global__ void stats_kernel(const float* __restrict__ A, float* __restrict__ gsum,
                             float* __restrict__ gsq)
{
    __shared__ float ssum[CH], ssq[CH];
    const int tid = threadIdx.x;
    if (tid < CH) { ssum[tid] = 0.f; ssq[tid] = 0.f; }
    __syncthreads();
    const int warp = tid >> 5, lane = tid & 31;
    const int n0 = blockIdx.x * 128;
    float ps[4] = {0, 0, 0, 0}, pq[4] = {0, 0, 0, 0};
    for (int r = warp; r < 128; r += 8) {
        const float* row = &A[(size_t)(n0 + r) * CH];
        #pragma unroll
        for (int c = 0; c < 4; c++) {
            float v = row[lane + c * 32];
            ps[c] += v; pq[c] += v * v;
        }
    }
    #pragma unroll
    for (int c = 0; c < 4; c++) {
        atomicAdd(&ssum[lane + c * 32], ps[c]);
        atomicAdd(&ssq[lane + c * 32], pq[c]);
    }
    __syncthreads();
    if (tid < CH) { atomicAdd(&gsum[tid], ssum[tid]); atomicAdd(&gsq[tid], ssq[tid]); }
}

__global__ void finalize_kernel(const float* __restrict__ gsum, const float* __restrict__ gsq,
                                float* __restrict__ mean, float* __restrict__ istd)
{
    int c = threadIdx.x;
    if (c < CH) {
        float m = gsum[c] * (1.f / (float)NTOK);
        float v = gsq[c] * (1.f / (float)NTOK) - m * m;
        mean[c] = m;
        istd[c] = rsqrtf(v + 1e-5f);
    }
}

// ---------------- normalize + transpose (N,C) -> (C,N) ----------------
__global__ void tnorm_kernel(const float* __restrict__ A, const float* __restrict__ mean,
                             const float* __restrict__ istd, float* __restrict__ out)
{
    __shared__ float tile[32][33];
    const int n0 = blockIdx.x * 32, c0 = blockIdx.y * 32;
    const int tx = threadIdx.x, ty = threadIdx.y;  // (32, 8)
    #pragma unroll
    for (int i = 0; i < 4; i++) {
        int nn = ty + i * 8;
        tile[nn][tx] = A[(size_t)(n0 + nn) * CH + c0 + tx];
    }
    __syncthreads();
    #pragma unroll
    for (int i = 0; i < 4; i++) {
        int cc = ty + i * 8;
        int c = c0 + cc;
        out[(size_t)c * NTOK + (n0 + tx)] = (tile[tx][cc] - mean[c]) * istd[c];
    }
}

// ---------------- launch ----------------
extern "C" void kernel_launch(void* const* d_in, const int* in_sizes, int n_in,
                              void* d_out, int out_size)
{
    const float* x      = (const float*)d_in[0];  // (C, N) = (128, 32768)
    const float* w_qkv  = (const float*)d_in[1];
    const float* b_qkv  = (const float*)d_in[2];
    const float* rpb    = (const float*)d_in[3];
    const float* w_proj = (const float*)d_in[4];
    const float* b_proj = (const float*)d_in[5];
    const float* w_ffn1 = (const float*)d_in[6];
    const float* b_ffn1 = (const float*)d_in[7];
    const float* w_ffn2 = (const float*)d_in[8];
    const float* b_ffn2 = (const float*)d_in[9];
    float* out = (float*)d_out;

    float *p_xT, *p_qkv, *p_attn, *p_y, *p_h, *p_z;
    float *p_sum1, *p_sq1, *p_sum2, *p_sq2, *p_m1, *p_i1, *p_m2, *p_i2;
    cudaGetSymbolAddress((void**)&p_xT,   g_xT);
    cudaGetSymbolAddress((void**)&p_qkv,  g_qkv);
    cudaGetSymbolAddress((void**)&p_attn, g_attn);
    cudaGetSymbolAddress((void**)&p_y,    g_y);
    cudaGetSymbolAddress((void**)&p_h,    g_h);
    cudaGetSymbolAddress((void**)&p_z,    g_z);
    cudaGetSymbolAddress((void**)&p_sum1, g_sum1);
    cudaGetSymbolAddress((void**)&p_sq1,  g_sq1);
    cudaGetSymbolAddress((void**)&p_sum2, g_sum2);
    cudaGetSymbolAddress((void**)&p_sq2,  g_sq2);
    cudaGetSymbolAddress((void**)&p_m1,   g_m1);
    cudaGetSymbolAddress((void**)&p_i1,   g_i1);
    cudaGetSymbolAddress((void**)&p_m2,   g_m2);
    cudaGetSymbolAddress((void**)&p_i2,   g_i2);

    cudaFuncSetAttribute(gemm_tc<false, 0>, cudaFuncAttributeMaxDynamicSharedMemorySize, SMEM_BYTES);
    cudaFuncSetAttribute(gemm_tc<true, 1>,  cudaFuncAttributeMaxDynamicSharedMemorySize, SMEM_BYTES);
    cudaFuncSetAttribute(gemm_tc<false, 2>, cudaFuncAttributeMaxDynamicSharedMemorySize, SMEM_BYTES);

    zero_stats_kernel<<<1, 128>>>();
    transpose_x_kernel<<<dim3(NTOK / 32, CH / 32), dim3(32, 8)>>>(x, p_xT);

    // QKV: g_xT (N,128) @ w_qkv^T -> g_qkv (N,384)
    gemm_tc<false, 0><<<dim3(NTOK / 128, JQKV / 64), 128, SMEM_BYTES>>>(
        p_xT, w_qkv, b_qkv, p_qkv, NTOK, CH, JQKV, nullptr, nullptr, nullptr);

    // attention -> g_attn (N,128)
    attn_kernel<<<NTOK / 8, 256>>>(p_qkv, rpb, p_attn);

    // proj: g_attn @ w_proj^T -> g_y (N,128)
    gemm_tc<false, 0><<<dim3(NTOK / 128, CH / 64), 128, SMEM_BYTES>>>(
        p_attn, w_proj, b_proj, p_y, NTOK, CH, CH, nullptr, nullptr, nullptr);

    // instance-norm #1 stats on g_y
    stats_kernel<<<NTOK / 128, 256>>>(p_y, p_sum1, p_sq1);
    finalize_kernel<<<1, 128>>>(p_sum1, p_sq1, p_m1, p_i1);

    // FFN1: normalize(g_y) @ w_ffn1^T, gelu -> g_h (N,512)
    gemm_tc<true, 1><<<dim3(NTOK / 128, CF / 64), 128, SMEM_BYTES>>>(
        p_y, w_ffn1, b_ffn1, p_h, NTOK, CH, CF, p_m1, p_i1, nullptr);

    // FFN2: g_h @ w_ffn2^T + bias + normalize(g_y) residual -> g_z (N,128)
    gemm_tc<false, 2><<<dim3(NTOK / 128, CH / 64), 128, SMEM_BYTES>>>(
        p_h, w_ffn2, b_ffn2, p_z, NTOK, CF, CH, p_m1, p_i1, p_y);

    // instance-norm #2 stats on g_z
    stats_kernel<<<NTOK / 128, 256>>>(p_z, p_sum2, p_sq2);
    finalize_kernel<<<1, 128>>>(p_sum2, p_sq2, p_m2, p_i2);

    // normalize + transpose to (C, N)
    tnorm_kernel<<<dim3(NTOK / 32, CH / 32), dim3(32, 8)>>>(p_z, p_m2, p_i2, out);
}

// round 7
// speedup vs baseline: 1.0565x; 1.0565x over previous
#include <cuda_runtime.h>
#include <math.h>
#include <stdint.h>

#define NTOK  32768
#define CH    128
#define CF    512
#define JQKV  384
#define NHEADS 8
#define HD    16

// ---------------- scratch (device globals; no runtime allocation) ----------------
__device__ float g_qkv[NTOK * JQKV];   // (N, 384) row-major
__device__ float g_attn[NTOK * CH];    // (N, 128)
__device__ float g_y[NTOK * CH];       // proj out (N, 128)
__device__ float g_h[NTOK * CF];       // ffn hidden (N, 512)
__device__ float g_z[NTOK * CH];       // ffn out + residual (N, 128)
__device__ float g_sum1[CH], g_sq1[CH], g_sum2[CH], g_sq2[CH];
__device__ float g_m1[CH], g_i1[CH], g_m2[CH], g_i2[CH];

// ---------------- zero stats ----------------
__global__ void zero_stats_kernel() {
    int t = threadIdx.x;
    if (t < CH) { g_sum1[t] = 0.f; g_sq1[t] = 0.f; g_sum2[t] = 0.f; g_sq2[t] = 0.f; }
}

// ---------------- TF32 helpers ----------------
__device__ __forceinline__ void split_tf32(float x, uint32_t& hi, uint32_t& lo) {
    uint32_t h;
    asm("cvt.rna.tf32.f32 %0, %1;" : "=r"(h) : "f"(x));
    float hf = __uint_as_float(h);
    uint32_t l;
    asm("cvt.rna.tf32.f32 %0, %1;" : "=r"(l) : "f"(x - hf));
    hi = h; lo = l;
}
__device__ __forceinline__ uint32_t cvt_tf32(float x) {
    uint32_t h;
    asm("cvt.rna.tf32.f32 %0, %1;" : "=r"(h) : "f"(x));
    return h;
}

__device__ __forceinline__ void mma_tf32(float c[4], const uint32_t a[4], const uint32_t b[2]) {
    asm volatile(
        "mma.sync.aligned.m16n8k8.row.col.f32.tf32.tf32.f32 "
        "{%0,%1,%2,%3}, {%4,%5,%6,%7}, {%8,%9}, {%0,%1,%2,%3};\n"
        : "+f"(c[0]), "+f"(c[1]), "+f"(c[2]), "+f"(c[3])
        : "r"(a[0]), "r"(a[1]), "r"(a[2]), "r"(a[3]), "r"(b[0]), "r"(b[1]));
}

// ---------------- tensor-core TF32 GEMM (NPASS-compensated) ----------------
// out[m][j] = sum_k A * W[j][k] + bias[j]
// AKM: A stored (K, M); else A stored (M, K)
// NORMA: normalize A values on load with nmean/nistd indexed by k
// EPI: 0 = bias; 1 = gelu(acc+bias); 2 = acc+bias + norm(res[m][j])
// NPASS: 1 = plain tf32; 2 = A split (hh+lh); 3 = full (hh+lh+hl)
// Block: 128 threads (4 warps), BM=128, BN=64, BK=32. Warp tile 64x32.
#define AS_STRIDE 136   // 136 % 32 == 8 -> conflict-free fragment loads
#define BS_STRIDE 72    // 72 % 32 == 8

template<bool AKM, bool NORMA, int EPI, int NPASS>
__global__ void __launch_bounds__(128) gemm_tc(const float* __restrict__ A,
                                               const float* __restrict__ W,
                                               const float* __restrict__ bias,
                                               float* __restrict__ out,
                                               int M, int Kd, int Jd,
                                               const float* __restrict__ nmean,
                                               const float* __restrict__ nistd,
                                               const float* __restrict__ res)
{
    __shared__ float As[32 * AS_STRIDE];
    __shared__ float Bs[32 * BS_STRIDE];

    const int tid  = threadIdx.x;
    const int wid  = tid >> 5, lane = tid & 31;
    const int l4   = lane >> 2, q = lane & 3;
    const int wm   = wid & 1, wn = wid >> 1;       // warp tile: rows wm*64, cols wn*32
    const int m0   = blockIdx.x * 128, j0 = blockIdx.y * 64;

    float c[4][4][4];
    #pragma unroll
    for (int mi = 0; mi < 4; mi++)
        #pragma unroll
        for (int ni = 0; ni < 4; ni++)
            #pragma unroll
            for (int r = 0; r < 4; r++) c[mi][ni][r] = 0.f;

    for (int k0 = 0; k0 < Kd; k0 += 32) {
        // ---- stage A tile (32 x 128) ----
        if (AKM) {
            #pragma unroll
            for (int i = 0; i < 8; i++) {
                int kk = wid * 8 + i;
                const float* src = &A[(size_t)(k0 + kk) * M + m0];
                #pragma unroll
                for (int cc = 0; cc < 4; cc++)
                    As[kk * AS_STRIDE + lane + 32 * cc] = src[lane + 32 * cc];
            }
        } else {
            const int mm = tid;
            const float* src = &A[(size_t)(m0 + mm) * Kd + k0];
            #pragma unroll
            for (int cc = 0; cc < 8; cc++) {
                float4 t4 = *(const float4*)(src + cc * 4);
                if (NORMA) {
                    int kb = k0 + cc * 4;
                    t4.x = (t4.x - nmean[kb + 0]) * nistd[kb + 0];
                    t4.y = (t4.y - nmean[kb + 1]) * nistd[kb + 1];
                    t4.z = (t4.z - nmean[kb + 2]) * nistd[kb + 2];
                    t4.w = (t4.w - nmean[kb + 3]) * nistd[kb + 3];
                }
                As[(cc * 4 + 0) * AS_STRIDE + mm] = t4.x;
                As[(cc * 4 + 1) * AS_STRIDE + mm] = t4.y;
                As[(cc * 4 + 2) * AS_STRIDE + mm] = t4.z;
                As[(cc * 4 + 3) * AS_STRIDE + mm] = t4.w;
            }
        }
        // ---- stage B tile (32 x 64): Bs[kk][nn] = W[j0+nn][k0+kk] ----
        {
            const int nn = tid >> 1, half = tid & 1;
            const float* src = &W[(size_t)(j0 + nn) * Kd + k0 + half * 16];
            #pragma unroll
            for (int cc = 0; cc < 4; cc++) {
                float4 t4 = *(const float4*)(src + cc * 4);
                int kk = half * 16 + cc * 4;
                Bs[(kk + 0) * BS_STRIDE + nn] = t4.x;
                Bs[(kk + 1) * BS_STRIDE + nn] = t4.y;
                Bs[(kk + 2) * BS_STRIDE + nn] = t4.z;
                Bs[(kk + 3) * BS_STRIDE + nn] = t4.w;
            }
        }
        __syncthreads();

        #pragma unroll
        for (int g = 0; g < 4; g++) {
            uint32_t bh[4][2], bl[4][2];
            #pragma unroll
            for (int ni = 0; ni < 4; ni++) {
                int col = wn * 32 + ni * 8 + l4;
                float f0 = Bs[(g * 8 + q) * BS_STRIDE + col];
                float f1 = Bs[(g * 8 + q + 4) * BS_STRIDE + col];
                if (NPASS >= 3) {
                    split_tf32(f0, bh[ni][0], bl[ni][0]);
                    split_tf32(f1, bh[ni][1], bl[ni][1]);
                } else {
                    bh[ni][0] = cvt_tf32(f0);
                    bh[ni][1] = cvt_tf32(f1);
                }
            }
            #pragma unroll
            for (int mi = 0; mi < 4; mi++) {
                int r0 = wm * 64 + mi * 16 + l4;
                float f0 = As[(g * 8 + q) * AS_STRIDE + r0];
                float f1 = As[(g * 8 + q) * AS_STRIDE + r0 + 8];
                float f2 = As[(g * 8 + q + 4) * AS_STRIDE + r0];
                float f3 = As[(g * 8 + q + 4) * AS_STRIDE + r0 + 8];
                uint32_t ah[4], al[4];
                if (NPASS >= 2) {
                    split_tf32(f0, ah[0], al[0]);
                    split_tf32(f1, ah[1], al[1]);
                    split_tf32(f2, ah[2], al[2]);
                    split_tf32(f3, ah[3], al[3]);
                } else {
                    ah[0] = cvt_tf32(f0);
                    ah[1] = cvt_tf32(f1);
                    ah[2] = cvt_tf32(f2);
                    ah[3] = cvt_tf32(f3);
                }
                #pragma unroll
                for (int ni = 0; ni < 4; ni++) {
                    mma_tf32(c[mi][ni], ah, bh[ni]);                   // hi*hi
                    if (NPASS >= 2) mma_tf32(c[mi][ni], al, bh[ni]);   // lo*hi
                    if (NPASS >= 3) mma_tf32(c[mi][ni], ah, bl[ni]);   // hi*lo
                }
            }
        }
        __syncthreads();
    }

    // ---- epilogue ----
    #pragma unroll
    for (int ni = 0; ni < 4; ni++) {
        int j = j0 + wn * 32 + ni * 8 + q * 2;
        float b0 = bias[j], b1 = bias[j + 1];
        float im0 = 0.f, ii0 = 0.f, im1 = 0.f, ii1 = 0.f;
        if (EPI == 2) { im0 = nmean[j]; ii0 = nistd[j]; im1 = nmean[j + 1]; ii1 = nistd[j + 1]; }
        #pragma unroll
        for (int mi = 0; mi < 4; mi++) {
            int r0 = m0 + wm * 64 + mi * 16 + l4;
            #pragma unroll
            for (int half = 0; half < 2; half++) {
                int m = r0 + half * 8;
                float v0 = c[mi][ni][half * 2 + 0] + b0;
                float v1 = c[mi][ni][half * 2 + 1] + b1;
                if (EPI == 1) {
                    float u = v0;
                    v0 = 0.5f * u * (1.f + tanhf(0.7978845608028654f * (u + 0.044715f * u * u * u)));
                    u = v1;
                    v1 = 0.5f * u * (1.f + tanhf(0.7978845608028654f * (u + 0.044715f * u * u * u)));
                } else if (EPI == 2) {
                    float2 r2 = *(const float2*)&res[(size_t)m * Jd + j];
                    v0 += (r2.x - im0) * ii0;
                    v1 += (r2.y - im1) * ii1;
                }
                *(float2*)&out[(size_t)m * Jd + j] = make_float2(v0, v1);
            }
        }
    }
}

// ---------------- neighborhood attention: one warp per token ----------------
__global__ void attn_kernel(const float* __restrict__ qkv, const float* __restrict__ rpb,
                            float* __restrict__ out)
{
    __shared__ float rpb_s[NHEADS * 125];
    const int tid = threadIdx.x;
    for (int i = tid; i < NHEADS * 125; i += 256) rpb_s[i] = rpb[i];
    __syncthreads();

    const int warp = tid >> 5, lane = tid & 31;
    const int n = blockIdx.x * 8 + warp;
    const int h = lane >> 2, p = lane & 3;

    const int hh = n >> 10, ww = (n >> 5) & 31, zz = n & 31;
    const int sh = min(max(hh - 1, 0), 29);
    const int sw = min(max(ww - 1, 0), 29);
    const int sz = min(max(zz - 1, 0), 29);
    const int bh = sh - hh + 2, bw = sw - ww + 2, bz = sz - zz + 2;

    float4 q4 = *(const float4*)&qkv[(size_t)n * JQKV + h * 16 + p * 4];
    const float qx = q4.x * 0.25f, qy = q4.y * 0.25f, qz = q4.z * 0.25f, qw = q4.w * 0.25f;

    const float* rb = &rpb_s[h * 125];
    float s[27];
    #pragma unroll
    for (int j = 0; j < 27; j++) {
        int kh = j / 9, kw = (j / 3) % 3, kz = j % 3;
        int nb = ((sh + kh) << 10) + ((sw + kw) << 5) + (sz + kz);
        float4 k4 = *(const float4*)&qkv[(size_t)nb * JQKV + 128 + h * 16 + p * 4];
        float d = qx * k4.x + qy * k4.y + qz * k4.z + qw * k4.w;
        d += __shfl_xor_sync(0xffffffffu, d, 1);
        d += __shfl_xor_sync(0xffffffffu, d, 2);
        s[j] = d + rb[(bh + kh) * 25 + (bw + kw) * 5 + (bz + kz)];
    }

    float mx = -1e30f;
    #pragma unroll
    for (int j = 0; j < 27; j++) mx = fmaxf(mx, s[j]);
    float sum = 0.f;
    #pragma unroll
    for (int j = 0; j < 27; j++) { s[j] = expf(s[j] - mx); sum += s[j]; }
    const float inv = 1.f / sum;

    float ox = 0.f, oy = 0.f, oz = 0.f, ow = 0.f;
    #pragma unroll
    for (int j = 0; j < 27; j++) {
        int kh = j / 9, kw = (j / 3) % 3, kz = j % 3;
        int nb = ((sh + kh) << 10) + ((sw + kw) << 5) + (sz + kz);
        float4 v4 = *(const float4*)&qkv[(size_t)nb * JQKV + 256 + h * 16 + p * 4];
        float pj = s[j] * inv;
        ox = fmaf(pj, v4.x, ox); oy = fmaf(pj, v4.y, oy);
        oz = fmaf(pj, v4.z, oz); ow = fmaf(pj, v4.w, ow);
    }
    *(float4*)&out[(size_t)n * CH + h * 16 + p * 4] = make_float4(ox, oy, oz, ow);
}

// ---------------- per-channel sum/sumsq over tokens ----------------
__global__ void stats_kernel(const float* __restrict__ A, float* __restrict__ gsum,
                             float* __restrict__ gsq)
{
    __shared__ float ssum[CH], ssq[CH];
    const int tid = threadIdx.x;
    if (tid < CH) { ssum[tid] = 0.f; ssq[tid] = 0.f; }
    __syncthreads();
    const int warp = tid >> 5, lane = tid & 31;
    const int n0 = blockIdx.x * 128;
    float ps[4] = {0, 0, 0, 0}, pq[4] = {0, 0, 0, 0};
    for (int r = warp; r < 128; r += 8) {
        const float* row = &A[(size_t)(n0 + r) * CH];
        #pragma unroll
        for (int c = 0; c < 4; c++) {
            float v = row[lane + c * 32];
            ps[c] += v; pq[c] += v * v;
        }
    }
    #pragma unroll
    for (int c = 0; c < 4; c++) {
        atomicAdd(&ssum[lane + c * 32], ps[c]);
        atomicAdd(&ssq[lane + c * 32], pq[c]);
    }
    __syncthreads();
    if (tid < CH) { atomicAdd(&gsum[tid], ssum[tid]); atomicAdd(&gsq[tid], ssq[tid]); }
}

__global__ void finalize_kernel(const float* __restrict__ gsum, const float* __restrict__ gsq,
                                float* __restrict__ mean, float* __restrict__ istd)
{
    int c = threadIdx.x;
    if (c < CH) {
        float m = gsum[c] * (1.f / (float)NTOK);
        float v = gsq[c] * (1.f / (float)NTOK) - m * m;
        mean[c] = m;
        istd[c] = rsqrtf(v + 1e-5f);
    }
}

// ---------------- normalize + transpose (N,C) -> (C,N) ----------------
__global__ void tnorm_kernel(const float* __restrict__ A, const float* __restrict__ mean,
                             const float* __restrict__ istd, float* __restrict__ out)
{
    __shared__ float tile[32][33];
    const int n0 = blockIdx.x * 32, c0 = blockIdx.y * 32;
    const int tx = threadIdx.x, ty = threadIdx.y;  // (32, 8)
    #pragma unroll
    for (int i = 0; i < 4; i++) {
        int nn = ty + i * 8;
        tile[nn][tx] = A[(size_t)(n0 + nn) * CH + c0 + tx];
    }
    __syncthreads();
    #pragma unroll
    for (int i = 0; i < 4; i++) {
        int cc = ty + i * 8;
        int c = c0 + cc;
        out[(size_t)c * NTOK + (n0 + tx)] = (tile[tx][cc] - mean[c]) * istd[c];
    }
}

// ---------------- launch ----------------
extern "C" void kernel_launch(void* const* d_in, const int* in_sizes, int n_in,
                              void* d_out, int out_size)
{
    const float* x      = (const float*)d_in[0];  // (C, N) = (128, 32768)
    const float* w_qkv  = (const float*)d_in[1];  // (384, 128)
    const float* b_qkv  = (const float*)d_in[2];
    const float* rpb    = (const float*)d_in[3];  // (8, 5, 5, 5)
    const float* w_proj = (const float*)d_in[4];  // (128, 128)
    const float* b_proj = (const float*)d_in[5];
    const float* w_ffn1 = (const float*)d_in[6];  // (512, 128)
    const float* b_ffn1 = (const float*)d_in[7];
    const float* w_ffn2 = (const float*)d_in[8];  // (128, 512)
    const float* b_ffn2 = (const float*)d_in[9];
    float* out = (float*)d_out;

    float *p_qkv, *p_attn, *p_y, *p_h, *p_z;
    float *p_sum1, *p_sq1, *p_sum2, *p_sq2, *p_m1, *p_i1, *p_m2, *p_i2;
    cudaGetSymbolAddress((void**)&p_qkv,  g_qkv);
    cudaGetSymbolAddress((void**)&p_attn, g_attn);
    cudaGetSymbolAddress((void**)&p_y,    g_y);
    cudaGetSymbolAddress((void**)&p_h,    g_h);
    cudaGetSymbolAddress((void**)&p_z,    g_z);
    cudaGetSymbolAddress((void**)&p_sum1, g_sum1);
    cudaGetSymbolAddress((void**)&p_sq1,  g_sq1);
    cudaGetSymbolAddress((void**)&p_sum2, g_sum2);
    cudaGetSymbolAddress((void**)&p_sq2,  g_sq2);
    cudaGetSymbolAddress((void**)&p_m1,   g_m1);
    cudaGetSymbolAddress((void**)&p_i1,   g_i1);
    cudaGetSymbolAddress((void**)&p_m2,   g_m2);
    cudaGetSymbolAddress((void**)&p_i2,   g_i2);

    zero_stats_kernel<<<1, 128>>>();

    // QKV: A = x (K-major, (128, 32768)) -> g_qkv (N, 384)   [2-pass: protects attention]
    gemm_tc<true, false, 0, 2><<<dim3(NTOK / 128, JQKV / 64), 128>>>(
        x, w_qkv, b_qkv, p_qkv, NTOK, CH, JQKV, nullptr, nullptr, nullptr);

    // attention -> g_attn (N, 128)
    attn_kernel<<<NTOK / 8, 256>>>(p_qkv, rpb, p_attn);

    // proj: g_attn (N,128) @ w_proj^T -> g_y (N,128)   [1-pass]
    gemm_tc<false, false, 0, 1><<<dim3(NTOK / 128, CH / 64), 128>>>(
        p_attn, w_proj, b_proj, p_y, NTOK, CH, CH, nullptr, nullptr, nullptr);

    // instance-norm #1 stats on g_y
    stats_kernel<<<NTOK / 128, 256>>>(p_y, p_sum1, p_sq1);
    finalize_kernel<<<1, 128>>>(p_sum1, p_sq1, p_m1, p_i1);

    // FFN1: normalize(g_y) @ w_ffn1^T, gelu -> g_h (N,512)   [1-pass]
    gemm_tc<false, true, 1, 1><<<dim3(NTOK / 128, CF / 64), 128>>>(
        p_y, w_ffn1, b_ffn1, p_h, NTOK, CH, CF, p_m1, p_i1, nullptr);

    // FFN2: g_h @ w_ffn2^T + bias + normalize(g_y) residual -> g_z (N,128)   [1-pass]
    gemm_tc<false, false, 2, 1><<<dim3(NTOK / 128, CH / 64), 128>>>(
        p_h, w_ffn2, b_ffn2, p_z, NTOK, CF, CH, p_m1, p_i1, p_y);

    // instance-norm #2 stats on g_z
    stats_kernel<<<NTOK / 128, 256>>>(p_z, p_sum2, p_sq2);
    finalize_kernel<<<1, 128>>>(p_sum2, p_sq2, p_m2, p_i2);

    // normalize + transpose to (C, N)
    tnorm_kernel<<<dim3(NTOK / 32, CH / 32), dim3(32, 8)>>>(p_z, p_m2, p_i2, out);
}

// round 8
// speedup vs baseline: 1.6036x; 1.5179x over previous
#include <cuda_runtime.h>
#include <math.h>
#include <stdint.h>

#define NTOK  32768
#define CH    128
#define CF    512
#define JQKV  384
#define NHEADS 8
#define HD    16

// ---------------- scratch (device globals; no runtime allocation) ----------------
__device__ float g_qkv[NTOK * JQKV];   // (N, 384) row-major
__device__ float g_attn[NTOK * CH];    // (N, 128)
__device__ float g_y[NTOK * CH];       // proj out (N, 128)
__device__ float g_h[NTOK * CF];       // ffn hidden (N, 512)
__device__ float g_z[NTOK * CH];       // ffn out + residual (N, 128)
__device__ float g_sum1[CH], g_sq1[CH], g_sum2[CH], g_sq2[CH];
__device__ float g_m1[CH], g_i1[CH], g_m2[CH], g_i2[CH];

// ---------------- zero stats ----------------
__global__ void zero_stats_kernel() {
    int t = threadIdx.x;
    if (t < CH) { g_sum1[t] = 0.f; g_sq1[t] = 0.f; g_sum2[t] = 0.f; g_sq2[t] = 0.f; }
}

// ---------------- TF32 helpers ----------------
__device__ __forceinline__ void split_tf32(float x, uint32_t& hi, uint32_t& lo) {
    uint32_t h;
    asm("cvt.rna.tf32.f32 %0, %1;" : "=r"(h) : "f"(x));
    float hf = __uint_as_float(h);
    uint32_t l;
    asm("cvt.rna.tf32.f32 %0, %1;" : "=r"(l) : "f"(x - hf));
    hi = h; lo = l;
}
__device__ __forceinline__ uint32_t cvt_tf32(float x) {
    uint32_t h;
    asm("cvt.rna.tf32.f32 %0, %1;" : "=r"(h) : "f"(x));
    return h;
}

__device__ __forceinline__ void mma_tf32(float c[4], const uint32_t a[4], const uint32_t b[2]) {
    asm volatile(
        "mma.sync.aligned.m16n8k8.row.col.f32.tf32.tf32.f32 "
        "{%0,%1,%2,%3}, {%4,%5,%6,%7}, {%8,%9}, {%0,%1,%2,%3};\n"
        : "+f"(c[0]), "+f"(c[1]), "+f"(c[2]), "+f"(c[3])
        : "r"(a[0]), "r"(a[1]), "r"(a[2]), "r"(a[3]), "r"(b[0]), "r"(b[1]));
}

// ---------------- tensor-core TF32 GEMM, register-prefetch pipelined ----------------
// out[m][j] = sum_k A * W[j][k] + bias[j]
// AKM: A stored (K, M); else A stored (M, K)
// NORMA: normalize A on store-to-smem (per-k mean/istd)
// EPI: 0 = bias; 1 = gelu; 2 = +norm residual
// NPASS: 1 = plain tf32; 2 = A split; 3 = full
// 256 threads (8 warps), BM=128, BN=64, BK=32. Warp grid 4(m) x 2(n), warp tile 32x32.
#define AS_STRIDE 136   // 136 % 32 == 8 -> conflict-free fragment loads
#define BS_STRIDE 72    // 72 % 32 == 8

template<bool AKM, bool NORMA, int EPI, int NPASS>
__global__ void __launch_bounds__(256) gemm_tc(const float* __restrict__ A,
                                               const float* __restrict__ W,
                                               const float* __restrict__ bias,
                                               float* __restrict__ out,
                                               int M, int Kd, int Jd,
                                               const float* __restrict__ nmean,
                                               const float* __restrict__ nistd,
                                               const float* __restrict__ res)
{
    __shared__ float As[32 * AS_STRIDE];
    __shared__ float Bs[32 * BS_STRIDE];

    const int tid  = threadIdx.x;
    const int wid  = tid >> 5, lane = tid & 31;
    const int l4   = lane >> 2, q = lane & 3;
    const int wm   = wid & 3, wn = wid >> 2;       // warp tile: rows wm*32, cols wn*32
    const int m0   = blockIdx.x * 128, j0 = blockIdx.y * 64;

    // staging decomposition (256 threads)
    const int a_kk = tid >> 3, a_mg = (tid & 7) * 16;   // AKM: row k, 16 m-cols
    const int a_mm = tid >> 1, a_kh = (tid & 1) * 16;   // MK : row m, 16 k-cols
    const int b_nn = tid >> 2, b_kq = (tid & 3) * 8;    //      row n, 8 k-cols

    float4 pa[4], pb[2];

    auto prefetch = [&](int k0) {
        if (AKM) {
            const float* src = &A[(size_t)(k0 + a_kk) * M + m0 + a_mg];
            #pragma unroll
            for (int i = 0; i < 4; i++) pa[i] = *(const float4*)(src + i * 4);
        } else {
            const float* src = &A[(size_t)(m0 + a_mm) * Kd + k0 + a_kh];
            #pragma unroll
            for (int i = 0; i < 4; i++) pa[i] = *(const float4*)(src + i * 4);
        }
        const float* srcb = &W[(size_t)(j0 + b_nn) * Kd + k0 + b_kq];
        #pragma unroll
        for (int i = 0; i < 2; i++) pb[i] = *(const float4*)(srcb + i * 4);
    };

    auto store_stage = [&](int k0) {
        if (AKM) {
            #pragma unroll
            for (int i = 0; i < 4; i++)
                *(float4*)&As[a_kk * AS_STRIDE + a_mg + i * 4] = pa[i];
        } else {
            #pragma unroll
            for (int i = 0; i < 4; i++) {
                float4 t4 = pa[i];
                int kb = a_kh + i * 4;
                if (NORMA) {
                    t4.x = (t4.x - nmean[k0 + kb + 0]) * nistd[k0 + kb + 0];
                    t4.y = (t4.y - nmean[k0 + kb + 1]) * nistd[k0 + kb + 1];
                    t4.z = (t4.z - nmean[k0 + kb + 2]) * nistd[k0 + kb + 2];
                    t4.w = (t4.w - nmean[k0 + kb + 3]) * nistd[k0 + kb + 3];
                }
                As[(kb + 0) * AS_STRIDE + a_mm] = t4.x;
                As[(kb + 1) * AS_STRIDE + a_mm] = t4.y;
                As[(kb + 2) * AS_STRIDE + a_mm] = t4.z;
                As[(kb + 3) * AS_STRIDE + a_mm] = t4.w;
            }
        }
        #pragma unroll
        for (int i = 0; i < 2; i++) {
            float4 t4 = pb[i];
            int kb = b_kq + i * 4;
            Bs[(kb + 0) * BS_STRIDE + b_nn] = t4.x;
            Bs[(kb + 1) * BS_STRIDE + b_nn] = t4.y;
            Bs[(kb + 2) * BS_STRIDE + b_nn] = t4.z;
            Bs[(kb + 3) * BS_STRIDE + b_nn] = t4.w;
        }
    };

    float c[2][4][4];
    #pragma unroll
    for (int mi = 0; mi < 2; mi++)
        #pragma unroll
        for (int ni = 0; ni < 4; ni++)
            #pragma unroll
            for (int r = 0; r < 4; r++) c[mi][ni][r] = 0.f;

    const int nT = Kd >> 5;
    prefetch(0);

    for (int t = 0; t < nT; t++) {
        const int k0 = t << 5;
        __syncthreads();           // previous compute done, safe to overwrite smem
        store_stage(k0);
        __syncthreads();
        if (t + 1 < nT) prefetch((t + 1) << 5);   // LDGs in flight during compute

        #pragma unroll
        for (int g = 0; g < 4; g++) {
            uint32_t bh[4][2], bl[4][2];
            #pragma unroll
            for (int ni = 0; ni < 4; ni++) {
                int col = wn * 32 + ni * 8 + l4;
                float f0 = Bs[(g * 8 + q) * BS_STRIDE + col];
                float f1 = Bs[(g * 8 + q + 4) * BS_STRIDE + col];
                if (NPASS >= 3) {
                    split_tf32(f0, bh[ni][0], bl[ni][0]);
                    split_tf32(f1, bh[ni][1], bl[ni][1]);
                } else {
                    bh[ni][0] = cvt_tf32(f0);
                    bh[ni][1] = cvt_tf32(f1);
                }
            }
            #pragma unroll
            for (int mi = 0; mi < 2; mi++) {
                int r0 = wm * 32 + mi * 16 + l4;
                float f0 = As[(g * 8 + q) * AS_STRIDE + r0];
                float f1 = As[(g * 8 + q) * AS_STRIDE + r0 + 8];
                float f2 = As[(g * 8 + q + 4) * AS_STRIDE + r0];
                float f3 = As[(g * 8 + q + 4) * AS_STRIDE + r0 + 8];
                uint32_t ah[4], al[4];
                if (NPASS >= 2) {
                    split_tf32(f0, ah[0], al[0]);
                    split_tf32(f1, ah[1], al[1]);
                    split_tf32(f2, ah[2], al[2]);
                    split_tf32(f3, ah[3], al[3]);
                } else {
                    ah[0] = cvt_tf32(f0);
                    ah[1] = cvt_tf32(f1);
                    ah[2] = cvt_tf32(f2);
                    ah[3] = cvt_tf32(f3);
                }
                #pragma unroll
                for (int ni = 0; ni < 4; ni++) {
                    mma_tf32(c[mi][ni], ah, bh[ni]);                   // hi*hi
                    if (NPASS >= 2) mma_tf32(c[mi][ni], al, bh[ni]);   // lo*hi
                    if (NPASS >= 3) mma_tf32(c[mi][ni], ah, bl[ni]);   // hi*lo
                }
            }
        }
    }

    // ---- epilogue ----
    #pragma unroll
    for (int ni = 0; ni < 4; ni++) {
        int j = j0 + wn * 32 + ni * 8 + q * 2;
        float b0 = bias[j], b1 = bias[j + 1];
        float im0 = 0.f, ii0 = 0.f, im1 = 0.f, ii1 = 0.f;
        if (EPI == 2) { im0 = nmean[j]; ii0 = nistd[j]; im1 = nmean[j + 1]; ii1 = nistd[j + 1]; }
        #pragma unroll
        for (int mi = 0; mi < 2; mi++) {
            int r0 = m0 + wm * 32 + mi * 16 + l4;
            #pragma unroll
            for (int half = 0; half < 2; half++) {
                int m = r0 + half * 8;
                float v0 = c[mi][ni][half * 2 + 0] + b0;
                float v1 = c[mi][ni][half * 2 + 1] + b1;
                if (EPI == 1) {
                    float u = v0;
                    v0 = 0.5f * u * (1.f + tanhf(0.7978845608028654f * (u + 0.044715f * u * u * u)));
                    u = v1;
                    v1 = 0.5f * u * (1.f + tanhf(0.7978845608028654f * (u + 0.044715f * u * u * u)));
                } else if (EPI == 2) {
                    float2 r2 = *(const float2*)&res[(size_t)m * Jd + j];
                    v0 += (r2.x - im0) * ii0;
                    v1 += (r2.y - im1) * ii1;
                }
                *(float2*)&out[(size_t)m * Jd + j] = make_float2(v0, v1);
            }
        }
    }
}

// ---------------- neighborhood attention: one warp per token ----------------
__global__ void attn_kernel(const float* __restrict__ qkv, const float* __restrict__ rpb,
                            float* __restrict__ out)
{
    __shared__ float rpb_s[NHEADS * 125];
    const int tid = threadIdx.x;
    for (int i = tid; i < NHEADS * 125; i += 256) rpb_s[i] = rpb[i];
    __syncthreads();

    const int warp = tid >> 5, lane = tid & 31;
    const int n = blockIdx.x * 8 + warp;
    const int h = lane >> 2, p = lane & 3;

    const int hh = n >> 10, ww = (n >> 5) & 31, zz = n & 31;
    const int sh = min(max(hh - 1, 0), 29);
    const int sw = min(max(ww - 1, 0), 29);
    const int sz = min(max(zz - 1, 0), 29);
    const int bh = sh - hh + 2, bw = sw - ww + 2, bz = sz - zz + 2;

    float4 q4 = *(const float4*)&qkv[(size_t)n * JQKV + h * 16 + p * 4];
    const float qx = q4.x * 0.25f, qy = q4.y * 0.25f, qz = q4.z * 0.25f, qw = q4.w * 0.25f;

    const float* rb = &rpb_s[h * 125];
    float s[27];
    #pragma unroll
    for (int j = 0; j < 27; j++) {
        int kh = j / 9, kw = (j / 3) % 3, kz = j % 3;
        int nb = ((sh + kh) << 10) + ((sw + kw) << 5) + (sz + kz);
        float4 k4 = *(const float4*)&qkv[(size_t)nb * JQKV + 128 + h * 16 + p * 4];
        float d = qx * k4.x + qy * k4.y + qz * k4.z + qw * k4.w;
        d += __shfl_xor_sync(0xffffffffu, d, 1);
        d += __shfl_xor_sync(0xffffffffu, d, 2);
        s[j] = d + rb[(bh + kh) * 25 + (bw + kw) * 5 + (bz + kz)];
    }

    float mx = -1e30f;
    #pragma unroll
    for (int j = 0; j < 27; j++) mx = fmaxf(mx, s[j]);
    float sum = 0.f;
    #pragma unroll
    for (int j = 0; j < 27; j++) { s[j] = expf(s[j] - mx); sum += s[j]; }
    const float inv = 1.f / sum;

    float ox = 0.f, oy = 0.f, oz = 0.f, ow = 0.f;
    #pragma unroll
    for (int j = 0; j < 27; j++) {
        int kh = j / 9, kw = (j / 3) % 3, kz = j % 3;
        int nb = ((sh + kh) << 10) + ((sw + kw) << 5) + (sz + kz);
        float4 v4 = *(const float4*)&qkv[(size_t)nb * JQKV + 256 + h * 16 + p * 4];
        float pj = s[j] * inv;
        ox = fmaf(pj, v4.x, ox); oy = fmaf(pj, v4.y, oy);
        oz = fmaf(pj, v4.z, oz); ow = fmaf(pj, v4.w, ow);
    }
    *(float4*)&out[(size_t)n * CH + h * 16 + p * 4] = make_float4(ox, oy, oz, ow);
}

// ---------------- per-channel sum/sumsq over tokens ----------------
__global__ void stats_kernel(const float* __restrict__ A, float* __restrict__ gsum,
                             float* __restrict__ gsq)
{
    __shared__ float ssum[CH], ssq[CH];
    const int tid = threadIdx.x;
    if (tid < CH) { ssum[tid] = 0.f; ssq[tid] = 0.f; }
    __syncthreads();
    const int warp = tid >> 5, lane = tid & 31;
    const int n0 = blockIdx.x * 128;
    float ps[4] = {0, 0, 0, 0}, pq[4] = {0, 0, 0, 0};
    for (int r = warp; r < 128; r += 8) {
        const float* row = &A[(size_t)(n0 + r) * CH];
        #pragma unroll
        for (int c = 0; c < 4; c++) {
            float v = row[lane + c * 32];
            ps[c] += v; pq[c] += v * v;
        }
    }
    #pragma unroll
    for (int c = 0; c < 4; c++) {
        atomicAdd(&ssum[lane + c * 32], ps[c]);
        atomicAdd(&ssq[lane + c * 32], pq[c]);
    }
    __syncthreads();
    if (tid < CH) { atomicAdd(&gsum[tid], ssum[tid]); atomicAdd(&gsq[tid], ssq[tid]); }
}

__global__ void finalize_kernel(const float* __restrict__ gsum, const float* __restrict__ gsq,
                                float* __restrict__ mean, float* __restrict__ istd)
{
    int c = threadIdx.x;
    if (c < CH) {
        float m = gsum[c] * (1.f / (float)NTOK);
        float v = gsq[c] * (1.f / (float)NTOK) - m * m;
        mean[c] = m;
        istd[c] = rsqrtf(v + 1e-5f);
    }
}

// ---------------- normalize + transpose (N,C) -> (C,N) ----------------
__global__ void tnorm_kernel(const float* __restrict__ A, const float* __restrict__ mean,
                             const float* __restrict__ istd, float* __restrict__ out)
{
    __shared__ float tile[32][33];
    const int n0 = blockIdx.x * 32, c0 = blockIdx.y * 32;
    const int tx = threadIdx.x, ty = threadIdx.y;  // (32, 8)
    #pragma unroll
    for (int i = 0; i < 4; i++) {
        int nn = ty + i * 8;
        tile[nn][tx] = A[(size_t)(n0 + nn) * CH + c0 + tx];
    }
    __syncthreads();
    #pragma unroll
    for (int i = 0; i < 4; i++) {
        int cc = ty + i * 8;
        int c = c0 + cc;
        out[(size_t)c * NTOK + (n0 + tx)] = (tile[tx][cc] - mean[c]) * istd[c];
    }
}

// ---------------- launch ----------------
extern "C" void kernel_launch(void* const* d_in, const int* in_sizes, int n_in,
                              void* d_out, int out_size)
{
    const float* x      = (const float*)d_in[0];  // (C, N) = (128, 32768)
    const float* w_qkv  = (const float*)d_in[1];  // (384, 128)
    const float* b_qkv  = (const float*)d_in[2];
    const float* rpb    = (const float*)d_in[3];  // (8, 5, 5, 5)
    const float* w_proj = (const float*)d_in[4];  // (128, 128)
    const float* b_proj = (const float*)d_in[5];
    const float* w_ffn1 = (const float*)d_in[6];  // (512, 128)
    const float* b_ffn1 = (const float*)d_in[7];
    const float* w_ffn2 = (const float*)d_in[8];  // (128, 512)
    const float* b_ffn2 = (const float*)d_in[9];
    float* out = (float*)d_out;

    float *p_qkv, *p_attn, *p_y, *p_h, *p_z;
    float *p_sum1, *p_sq1, *p_sum2, *p_sq2, *p_m1, *p_i1, *p_m2, *p_i2;
    cudaGetSymbolAddress((void**)&p_qkv,  g_qkv);
    cudaGetSymbolAddress((void**)&p_attn, g_attn);
    cudaGetSymbolAddress((void**)&p_y,    g_y);
    cudaGetSymbolAddress((void**)&p_h,    g_h);
    cudaGetSymbolAddress((void**)&p_z,    g_z);
    cudaGetSymbolAddress((void**)&p_sum1, g_sum1);
    cudaGetSymbolAddress((void**)&p_sq1,  g_sq1);
    cudaGetSymbolAddress((void**)&p_sum2, g_sum2);
    cudaGetSymbolAddress((void**)&p_sq2,  g_sq2);
    cudaGetSymbolAddress((void**)&p_m1,   g_m1);
    cudaGetSymbolAddress((void**)&p_i1,   g_i1);
    cudaGetSymbolAddress((void**)&p_m2,   g_m2);
    cudaGetSymbolAddress((void**)&p_i2,   g_i2);

    zero_stats_kernel<<<1, 128>>>();

    // QKV: A = x (K-major, (128, 32768)) -> g_qkv (N, 384)   [2-pass: protects attention]
    gemm_tc<true, false, 0, 2><<<dim3(NTOK / 128, JQKV / 64), 256>>>(
        x, w_qkv, b_qkv, p_qkv, NTOK, CH, JQKV, nullptr, nullptr, nullptr);

    // attention -> g_attn (N, 128)
    attn_kernel<<<NTOK / 8, 256>>>(p_qkv, rpb, p_attn);

    // proj: g_attn (N,128) @ w_proj^T -> g_y (N,128)   [1-pass]
    gemm_tc<false, false, 0, 1><<<dim3(NTOK / 128, CH / 64), 256>>>(
        p_attn, w_proj, b_proj, p_y, NTOK, CH, CH, nullptr, nullptr, nullptr);

    // instance-norm #1 stats on g_y
    stats_kernel<<<NTOK / 128, 256>>>(p_y, p_sum1, p_sq1);
    finalize_kernel<<<1, 128>>>(p_sum1, p_sq1, p_m1, p_i1);

    // FFN1: normalize(g_y) @ w_ffn1^T, gelu -> g_h (N,512)   [1-pass]
    gemm_tc<false, true, 1, 1><<<dim3(NTOK / 128, CF / 64), 256>>>(
        p_y, w_ffn1, b_ffn1, p_h, NTOK, CH, CF, p_m1, p_i1, nullptr);

    // FFN2: g_h @ w_ffn2^T + bias + normalize(g_y) residual -> g_z (N,128)   [1-pass]
    gemm_tc<false, false, 2, 1><<<dim3(NTOK / 128, CH / 64), 256>>>(
        p_h, w_ffn2, b_ffn2, p_z, NTOK, CF, CH, p_m1, p_i1, p_y);

    // instance-norm #2 stats on g_z
    stats_kernel<<<NTOK / 128, 256>>>(p_z, p_sum2, p_sq2);
    finalize_kernel<<<1, 128>>>(p_sum2, p_sq2, p_m2, p_i2);

    // normalize + transpose to (C, N)
    tnorm_kernel<<<dim3(NTOK / 32, CH / 32), dim3(32, 8)>>>(p_z, p_m2, p_i2, out);
}